// round 1
// baseline (speedup 1.0000x reference)
#include <cuda_runtime.h>
#include <cuda_bf16.h>
#include <math.h>

// ---------------- problem constants ----------------
#define NG      64      // graphs
#define PNODES  31
#define N_ORIG  1984
#define NN      2048    // total nodes
#define DD      512     // hidden
#define NH      8
#define DKH     64
#define FF      2048
#define NL      4
#define NF      32
#define MAX_SP  100
#define MAX_DEG 100

// ---------------- scratch (device globals, no allocs) ----------------
__device__ float g_B[(size_t)NN * NN];            // bias + mask (=-inf cross-graph)  16MB
__device__ float g_scores[(size_t)NH * NN * NN];  // attention logits/weights        134MB
__device__ float g_ff[(size_t)NN * FF];           // FFN hidden                       16MB
__device__ float g_h[NN * DD];
__device__ float g_hn[NN * DD];
__device__ float g_Q[NN * DD];
__device__ float g_K[NN * DD];
__device__ float g_V[NN * DD];
__device__ float g_attn[NN * DD];

// ---------------- B matrix (bias + -inf mask fused) ----------------
__global__ void build_B_kernel(const int* __restrict__ sp,
                               const int* __restrict__ bid,
                               const float* __restrict__ db,
                               const float* __restrict__ vb)
{
    size_t idx = (size_t)blockIdx.x * blockDim.x + threadIdx.x;
    if (idx >= (size_t)NN * NN) return;
    int i = (int)(idx / NN);
    int j = (int)(idx % NN);
    float v;
    if (bid[i] != bid[j]) {
        v = -INFINITY;                              // attention mask
    } else if (i == j) {
        v = db[0];                                  // diagonal
    } else {
        bool vi = i >= N_ORIG, vj = j >= N_ORIG;
        if (vi != vj)        v = vb[0];             // virtual edge
        else if (!vi)        v = db[min(sp[(size_t)i * N_ORIG + j], MAX_SP)];
        else                 v = db[MAX_SP + 1];    // fill (unreachable in practice)
    }
    g_B[idx] = v;
}

// ---------------- init: h = [xW+b ; 0] + cent_emb ----------------
__global__ void init_h_kernel(const float* __restrict__ x,
                              const float* __restrict__ W,
                              const float* __restrict__ b,
                              const float* __restrict__ cent,
                              const int* __restrict__ deg)
{
    int idx = blockIdx.x * blockDim.x + threadIdx.x;
    if (idx >= NN * DD) return;
    int n = idx / DD, d = idx % DD;
    float v = 0.f;
    if (n < N_ORIG) {
        v = b[d];
        #pragma unroll
        for (int f = 0; f < NF; f++)
            v += x[n * NF + f] * W[f * DD + d];
    }
    v += cent[min(deg[n], MAX_DEG) * DD + d];
    g_h[idx] = v;
}

// ---------------- layernorm (no affine, eps 1e-5) ----------------
__global__ void ln_kernel(const float* __restrict__ in, float* __restrict__ out)
{
    __shared__ float s1[256], s2[256];
    int row = blockIdx.x, t = threadIdx.x;
    const float* p = in + (size_t)row * DD;
    float a = 0.f, q = 0.f;
    for (int j = t; j < DD; j += 256) { float v = p[j]; a += v; q += v * v; }
    s1[t] = a; s2[t] = q; __syncthreads();
    for (int s = 128; s > 0; s >>= 1) {
        if (t < s) { s1[t] += s1[t + s]; s2[t] += s2[t + s]; }
        __syncthreads();
    }
    float mean = s1[0] * (1.f / DD);
    float var  = s2[0] * (1.f / DD) - mean * mean;
    float r = rsqrtf(var + 1e-5f);
    float* o = out + (size_t)row * DD;
    for (int j = t; j < DD; j += 256) o[j] = (p[j] - mean) * r;
}

// ---------------- row softmax over 2048 ----------------
__global__ void softmax_kernel(float* __restrict__ S)
{
    __shared__ float red[256];
    size_t row = blockIdx.x;
    float* p = S + row * NN;
    int t = threadIdx.x;
    float m = -INFINITY;
    for (int j = t; j < NN; j += 256) m = fmaxf(m, p[j]);
    red[t] = m; __syncthreads();
    for (int s = 128; s > 0; s >>= 1) { if (t < s) red[t] = fmaxf(red[t], red[t + s]); __syncthreads(); }
    m = red[0]; __syncthreads();
    float sum = 0.f;
    for (int j = t; j < NN; j += 256) { float e = __expf(p[j] - m); p[j] = e; sum += e; }
    red[t] = sum; __syncthreads();
    for (int s = 128; s > 0; s >>= 1) { if (t < s) red[t] += red[t + s]; __syncthreads(); }
    float inv = 1.f / red[0];
    for (int j = t; j < NN; j += 256) p[j] *= inv;
}

// ---------------- generic batched tiled GEMM, C = A*B (+bias)(+res)(relu) ----------------
// 64x64 tile, BK=16, 256 threads, 4x4 microtile. M,N %64==0, K %16==0.
template<bool RELU, bool RES>
__global__ void gemm_nn(const float* __restrict__ A, const float* __restrict__ B,
                        const float* __restrict__ bias, const float* __restrict__ res,
                        float* __restrict__ C,
                        int M, int N, int K, int lda, int ldb, int ldc,
                        long long sA, long long sB, long long sBias, long long sC)
{
    int z = blockIdx.z;
    A += (size_t)z * sA; B += (size_t)z * sB; C += (size_t)z * sC;
    if (bias) bias += (size_t)z * sBias;
    const float* resp = RES ? (res + (size_t)z * sC) : nullptr;

    __shared__ float As[16][65];
    __shared__ float Bs[16][65];
    int tid = threadIdx.x;
    int tx = tid & 15, ty = tid >> 4;
    int row0 = blockIdx.y * 64, col0 = blockIdx.x * 64;
    float acc[4][4] = {};

    for (int k0 = 0; k0 < K; k0 += 16) {
        #pragma unroll
        for (int i = 0; i < 4; i++) {
            int m = (tid >> 4) + i * 16;
            int kk = tid & 15;
            As[kk][m] = A[(size_t)(row0 + m) * lda + k0 + kk];
        }
        #pragma unroll
        for (int i = 0; i < 4; i++) {
            int kk = (tid >> 6) + i * 4;
            int n = tid & 63;
            Bs[kk][n] = B[(size_t)(k0 + kk) * ldb + col0 + n];
        }
        __syncthreads();
        #pragma unroll
        for (int kk = 0; kk < 16; kk++) {
            float a[4], b[4];
            #pragma unroll
            for (int i = 0; i < 4; i++) a[i] = As[kk][ty * 4 + i];
            #pragma unroll
            for (int j = 0; j < 4; j++) b[j] = Bs[kk][tx * 4 + j];
            #pragma unroll
            for (int i = 0; i < 4; i++)
                #pragma unroll
                for (int j = 0; j < 4; j++)
                    acc[i][j] += a[i] * b[j];
        }
        __syncthreads();
    }
    #pragma unroll
    for (int i = 0; i < 4; i++) {
        int r = row0 + ty * 4 + i;
        #pragma unroll
        for (int j = 0; j < 4; j++) {
            int c = col0 + tx * 4 + j;
            float v = acc[i][j];
            if (bias) v += bias[c];
            if (RES)  v += resp[(size_t)r * ldc + c];
            if (RELU) v = fmaxf(v, 0.f);
            C[(size_t)r * ldc + c] = v;
        }
    }
}

// ---------------- logits GEMM: C = alpha * A * B^T + bias2d (bias2d may be -inf) ----------------
__global__ void gemm_nt_bias2d(const float* __restrict__ A, const float* __restrict__ Bt,
                               const float* __restrict__ bias2d, float* __restrict__ C,
                               int M, int N, int K, int lda, int ldbt, int ldc, int ldbias,
                               long long sA, long long sBt, long long sC, float alpha)
{
    int z = blockIdx.z;
    A += (size_t)z * sA; Bt += (size_t)z * sBt; C += (size_t)z * sC;

    __shared__ float As[16][65];
    __shared__ float Bs[16][65];
    int tid = threadIdx.x;
    int tx = tid & 15, ty = tid >> 4;
    int row0 = blockIdx.y * 64, col0 = blockIdx.x * 64;
    float acc[4][4] = {};

    for (int k0 = 0; k0 < K; k0 += 16) {
        #pragma unroll
        for (int i = 0; i < 4; i++) {
            int m = (tid >> 4) + i * 16;
            int kk = tid & 15;
            As[kk][m] = A[(size_t)(row0 + m) * lda + k0 + kk];
        }
        #pragma unroll
        for (int i = 0; i < 4; i++) {
            int n = (tid >> 4) + i * 16;
            int kk = tid & 15;
            Bs[kk][n] = Bt[(size_t)(col0 + n) * ldbt + k0 + kk];
        }
        __syncthreads();
        #pragma unroll
        for (int kk = 0; kk < 16; kk++) {
            float a[4], b[4];
            #pragma unroll
            for (int i = 0; i < 4; i++) a[i] = As[kk][ty * 4 + i];
            #pragma unroll
            for (int j = 0; j < 4; j++) b[j] = Bs[kk][tx * 4 + j];
            #pragma unroll
            for (int i = 0; i < 4; i++)
                #pragma unroll
                for (int j = 0; j < 4; j++)
                    acc[i][j] += a[i] * b[j];
        }
        __syncthreads();
    }
    #pragma unroll
    for (int i = 0; i < 4; i++) {
        int r = row0 + ty * 4 + i;
        #pragma unroll
        for (int j = 0; j < 4; j++) {
            int c = col0 + tx * 4 + j;
            C[(size_t)r * ldc + c] = acc[i][j] * alpha + bias2d[(size_t)r * ldbias + c];
        }
    }
}

// ---------------- output copy: virtual node states ----------------
__global__ void copy_out_kernel(float* __restrict__ out)
{
    int i = blockIdx.x * blockDim.x + threadIdx.x;
    if (i < NG * DD) out[i] = g_h[N_ORIG * DD + i];
}

// ---------------- launch ----------------
extern "C" void kernel_launch(void* const* d_in, const int* in_sizes, int n_in,
                              void* d_out, int out_size)
{
    const float* x      = (const float*)d_in[0];
    const int*   sp     = (const int*)  d_in[1];
    const int*   bid    = (const int*)  d_in[2];
    const int*   deg    = (const int*)  d_in[3];
    const float* init_W = (const float*)d_in[4];
    const float* init_b = (const float*)d_in[5];
    const float* cent   = (const float*)d_in[6];
    const float* db     = (const float*)d_in[7];
    const float* vb     = (const float*)d_in[8];
    const float* Wq     = (const float*)d_in[9];
    const float* bq     = (const float*)d_in[10];
    const float* Wk     = (const float*)d_in[11];
    const float* bk     = (const float*)d_in[12];
    const float* Wv     = (const float*)d_in[13];
    const float* bv     = (const float*)d_in[14];
    const float* Wo     = (const float*)d_in[15];
    const float* bo     = (const float*)d_in[16];
    const float* W1     = (const float*)d_in[17];
    const float* b1     = (const float*)d_in[18];
    const float* W2     = (const float*)d_in[19];
    const float* b2     = (const float*)d_in[20];

    float *B, *h, *hn, *Q, *K, *V, *attn, *scores, *ff;
    cudaGetSymbolAddress((void**)&B,      g_B);
    cudaGetSymbolAddress((void**)&h,      g_h);
    cudaGetSymbolAddress((void**)&hn,     g_hn);
    cudaGetSymbolAddress((void**)&Q,      g_Q);
    cudaGetSymbolAddress((void**)&K,      g_K);
    cudaGetSymbolAddress((void**)&V,      g_V);
    cudaGetSymbolAddress((void**)&attn,   g_attn);
    cudaGetSymbolAddress((void**)&scores, g_scores);
    cudaGetSymbolAddress((void**)&ff,     g_ff);

    // B matrix (bias + mask)
    build_B_kernel<<<(NN * NN) / 256, 256>>>(sp, bid, db, vb);
    // init h
    init_h_kernel<<<(NN * DD) / 256, 256>>>(x, init_W, init_b, cent, deg);

    const float scale = 1.f / sqrtf((float)DKH);

    for (int l = 0; l < NL; l++) {
        // ---- attention ----
        ln_kernel<<<NN, 256>>>(h, hn);

        // QKV: per-head GEMM [2048,512]x[512,64], output packed [N, H*DK]
        {
            dim3 grid(1, NN / 64, NH);
            long long sB = (long long)DD * DKH, sBias = DKH, sC = DKH;
            gemm_nn<false, false><<<grid, 256>>>(hn, Wq + (size_t)l * NH * DD * DKH,
                bq + (size_t)l * NH * DKH, nullptr, Q,
                NN, DKH, DD, DD, DKH, DD, 0, sB, sBias, sC);
            gemm_nn<false, false><<<grid, 256>>>(hn, Wk + (size_t)l * NH * DD * DKH,
                bk + (size_t)l * NH * DKH, nullptr, K,
                NN, DKH, DD, DD, DKH, DD, 0, sB, sBias, sC);
            gemm_nn<false, false><<<grid, 256>>>(hn, Wv + (size_t)l * NH * DD * DKH,
                bv + (size_t)l * NH * DKH, nullptr, V,
                NN, DKH, DD, DD, DKH, DD, 0, sB, sBias, sC);
        }

        // logits = scale * Q K^T + B(mask)
        {
            dim3 grid(NN / 64, NN / 64, NH);
            gemm_nt_bias2d<<<grid, 256>>>(Q, K, B, scores,
                NN, NN, DKH, DD, DD, NN, NN,
                64LL, 64LL, (long long)NN * NN, scale);
        }

        // softmax rows
        softmax_kernel<<<NH * NN, 256>>>(scores);

        // attn_out = W * V   (packed [N, H*DK])
        {
            dim3 grid(1, NN / 64, NH);
            gemm_nn<false, false><<<grid, 256>>>(scores, V, nullptr, nullptr, attn,
                NN, DKH, NN, NN, DD, DD,
                (long long)NN * NN, 64LL, 0, 64LL);
        }

        // h = attn @ Wo + bo + h
        {
            dim3 grid(DD / 64, NN / 64, 1);
            gemm_nn<false, true><<<grid, 256>>>(attn, Wo + (size_t)l * DD * DD,
                bo + (size_t)l * DD, h, h,
                NN, DD, DD, DD, DD, DD, 0, 0, 0, 0);
        }

        // ---- FFN ----
        ln_kernel<<<NN, 256>>>(h, hn);
        {
            dim3 grid(FF / 64, NN / 64, 1);
            gemm_nn<true, false><<<grid, 256>>>(hn, W1 + (size_t)l * DD * FF,
                b1 + (size_t)l * FF, nullptr, ff,
                NN, FF, DD, DD, FF, FF, 0, 0, 0, 0);
        }
        {
            dim3 grid(DD / 64, NN / 64, 1);
            gemm_nn<false, true><<<grid, 256>>>(ff, W2 + (size_t)l * FF * DD,
                b2 + (size_t)l * DD, h, h,
                NN, DD, FF, FF, DD, DD, 0, 0, 0, 0);
        }
    }

    copy_out_kernel<<<(NG * DD) / 256, 256>>>((float*)d_out);
}

// round 2
// speedup vs baseline: 1.0025x; 1.0025x over previous
#include <cuda_runtime.h>
#include <cuda_bf16.h>
#include <math.h>

// ---------------- problem constants ----------------
#define NG      64      // graphs
#define PNODES  31
#define N_ORIG  1984
#define NN      2048    // total nodes
#define DD      512     // hidden
#define NH      8
#define DKH     64
#define FF      2048
#define NL      4
#define NF      32
#define MAX_SP  100
#define MAX_DEG 100

// ---------------- scratch (device globals, no allocs) ----------------
__device__ float g_B[(size_t)NN * NN];            // bias + mask (=-inf cross-graph)  16MB
__device__ float g_scores[(size_t)NH * NN * NN];  // attention logits/weights        134MB
__device__ float g_ff[(size_t)NN * FF];           // FFN hidden                       16MB
__device__ float g_h[NN * DD];
__device__ float g_hn[NN * DD];
__device__ float g_Q[NN * DD];
__device__ float g_K[NN * DD];
__device__ float g_V[NN * DD];
__device__ float g_attn[NN * DD];

// ---------------- B matrix (bias + -inf mask fused) ----------------
__global__ void build_B_kernel(const int* __restrict__ sp,
                               const int* __restrict__ bid,
                               const float* __restrict__ db,
                               const float* __restrict__ vb)
{
    size_t idx = (size_t)blockIdx.x * blockDim.x + threadIdx.x;
    if (idx >= (size_t)NN * NN) return;
    int i = (int)(idx / NN);
    int j = (int)(idx % NN);
    float v;
    if (bid[i] != bid[j]) {
        v = -INFINITY;                              // attention mask
    } else if (i == j) {
        v = db[0];                                  // diagonal
    } else {
        bool vi = i >= N_ORIG, vj = j >= N_ORIG;
        if (vi != vj)        v = vb[0];             // virtual edge
        else if (!vi)        v = db[min(sp[(size_t)i * N_ORIG + j], MAX_SP)];
        else                 v = db[MAX_SP + 1];    // fill (unreachable in practice)
    }
    g_B[idx] = v;
}

// ---------------- init: h = [xW+b ; 0] + cent_emb ----------------
__global__ void init_h_kernel(const float* __restrict__ x,
                              const float* __restrict__ W,
                              const float* __restrict__ b,
                              const float* __restrict__ cent,
                              const int* __restrict__ deg)
{
    int idx = blockIdx.x * blockDim.x + threadIdx.x;
    if (idx >= NN * DD) return;
    int n = idx / DD, d = idx % DD;
    float v = 0.f;
    if (n < N_ORIG) {
        v = b[d];
        #pragma unroll
        for (int f = 0; f < NF; f++)
            v += x[n * NF + f] * W[f * DD + d];
    }
    v += cent[min(deg[n], MAX_DEG) * DD + d];
    g_h[idx] = v;
}

// ---------------- layernorm (no affine, eps 1e-5) ----------------
__global__ void ln_kernel(const float* __restrict__ in, float* __restrict__ out)
{
    __shared__ float s1[256], s2[256];
    int row = blockIdx.x, t = threadIdx.x;
    const float* p = in + (size_t)row * DD;
    float a = 0.f, q = 0.f;
    for (int j = t; j < DD; j += 256) { float v = p[j]; a += v; q += v * v; }
    s1[t] = a; s2[t] = q; __syncthreads();
    for (int s = 128; s > 0; s >>= 1) {
        if (t < s) { s1[t] += s1[t + s]; s2[t] += s2[t + s]; }
        __syncthreads();
    }
    float mean = s1[0] * (1.f / DD);
    float var  = s2[0] * (1.f / DD) - mean * mean;
    float r = rsqrtf(var + 1e-5f);
    float* o = out + (size_t)row * DD;
    for (int j = t; j < DD; j += 256) o[j] = (p[j] - mean) * r;
}

// ---------------- row softmax over 2048 ----------------
__global__ void softmax_kernel(float* __restrict__ S)
{
    __shared__ float red[256];
    size_t row = blockIdx.x;
    float* p = S + row * NN;
    int t = threadIdx.x;
    float m = -INFINITY;
    for (int j = t; j < NN; j += 256) m = fmaxf(m, p[j]);
    red[t] = m; __syncthreads();
    for (int s = 128; s > 0; s >>= 1) { if (t < s) red[t] = fmaxf(red[t], red[t + s]); __syncthreads(); }
    m = red[0]; __syncthreads();
    float sum = 0.f;
    for (int j = t; j < NN; j += 256) { float e = __expf(p[j] - m); p[j] = e; sum += e; }
    red[t] = sum; __syncthreads();
    for (int s = 128; s > 0; s >>= 1) { if (t < s) red[t] += red[t + s]; __syncthreads(); }
    float inv = 1.f / red[0];
    for (int j = t; j < NN; j += 256) p[j] *= inv;
}

// ---------------- generic batched tiled GEMM, C = A*B (+bias)(+res)(relu) ----------------
// 64x64 tile, BK=16, 256 threads, 4x4 microtile. M,N %64==0, K %16==0.
template<bool RELU, bool RES>
__global__ void gemm_nn(const float* __restrict__ A, const float* __restrict__ B,
                        const float* __restrict__ bias, const float* __restrict__ res,
                        float* __restrict__ C,
                        int M, int N, int K, int lda, int ldb, int ldc,
                        long long sA, long long sB, long long sBias, long long sC)
{
    int z = blockIdx.z;
    A += (size_t)z * sA; B += (size_t)z * sB; C += (size_t)z * sC;
    if (bias) bias += (size_t)z * sBias;
    const float* resp = RES ? (res + (size_t)z * sC) : nullptr;

    __shared__ float As[16][65];
    __shared__ float Bs[16][65];
    int tid = threadIdx.x;
    int tx = tid & 15, ty = tid >> 4;
    int row0 = blockIdx.y * 64, col0 = blockIdx.x * 64;
    float acc[4][4] = {};

    for (int k0 = 0; k0 < K; k0 += 16) {
        #pragma unroll
        for (int i = 0; i < 4; i++) {
            int m = (tid >> 4) + i * 16;
            int kk = tid & 15;
            As[kk][m] = A[(size_t)(row0 + m) * lda + k0 + kk];
        }
        #pragma unroll
        for (int i = 0; i < 4; i++) {
            int kk = (tid >> 6) + i * 4;
            int n = tid & 63;
            Bs[kk][n] = B[(size_t)(k0 + kk) * ldb + col0 + n];
        }
        __syncthreads();
        #pragma unroll
        for (int kk = 0; kk < 16; kk++) {
            float a[4], b[4];
            #pragma unroll
            for (int i = 0; i < 4; i++) a[i] = As[kk][ty * 4 + i];
            #pragma unroll
            for (int j = 0; j < 4; j++) b[j] = Bs[kk][tx * 4 + j];
            #pragma unroll
            for (int i = 0; i < 4; i++)
                #pragma unroll
                for (int j = 0; j < 4; j++)
                    acc[i][j] += a[i] * b[j];
        }
        __syncthreads();
    }
    #pragma unroll
    for (int i = 0; i < 4; i++) {
        int r = row0 + ty * 4 + i;
        #pragma unroll
        for (int j = 0; j < 4; j++) {
            int c = col0 + tx * 4 + j;
            float v = acc[i][j];
            if (bias) v += bias[c];
            if (RES)  v += resp[(size_t)r * ldc + c];
            if (RELU) v = fmaxf(v, 0.f);
            C[(size_t)r * ldc + c] = v;
        }
    }
}

// ---------------- logits GEMM: C = alpha * A * B^T + bias2d (bias2d may be -inf) ----------------
__global__ void gemm_nt_bias2d(const float* __restrict__ A, const float* __restrict__ Bt,
                               const float* __restrict__ bias2d, float* __restrict__ C,
                               int M, int N, int K, int lda, int ldbt, int ldc, int ldbias,
                               long long sA, long long sBt, long long sC, float alpha)
{
    int z = blockIdx.z;
    A += (size_t)z * sA; Bt += (size_t)z * sBt; C += (size_t)z * sC;

    __shared__ float As[16][65];
    __shared__ float Bs[16][65];
    int tid = threadIdx.x;
    int tx = tid & 15, ty = tid >> 4;
    int row0 = blockIdx.y * 64, col0 = blockIdx.x * 64;
    float acc[4][4] = {};

    for (int k0 = 0; k0 < K; k0 += 16) {
        #pragma unroll
        for (int i = 0; i < 4; i++) {
            int m = (tid >> 4) + i * 16;
            int kk = tid & 15;
            As[kk][m] = A[(size_t)(row0 + m) * lda + k0 + kk];
        }
        #pragma unroll
        for (int i = 0; i < 4; i++) {
            int n = (tid >> 4) + i * 16;
            int kk = tid & 15;
            Bs[kk][n] = Bt[(size_t)(col0 + n) * ldbt + k0 + kk];
        }
        __syncthreads();
        #pragma unroll
        for (int kk = 0; kk < 16; kk++) {
            float a[4], b[4];
            #pragma unroll
            for (int i = 0; i < 4; i++) a[i] = As[kk][ty * 4 + i];
            #pragma unroll
            for (int j = 0; j < 4; j++) b[j] = Bs[kk][tx * 4 + j];
            #pragma unroll
            for (int i = 0; i < 4; i++)
                #pragma unroll
                for (int j = 0; j < 4; j++)
                    acc[i][j] += a[i] * b[j];
        }
        __syncthreads();
    }
    #pragma unroll
    for (int i = 0; i < 4; i++) {
        int r = row0 + ty * 4 + i;
        #pragma unroll
        for (int j = 0; j < 4; j++) {
            int c = col0 + tx * 4 + j;
            C[(size_t)r * ldc + c] = acc[i][j] * alpha + bias2d[(size_t)r * ldbias + c];
        }
    }
}

// ---------------- output copy: virtual node states ----------------
__global__ void copy_out_kernel(float* __restrict__ out)
{
    int i = blockIdx.x * blockDim.x + threadIdx.x;
    if (i < NG * DD) out[i] = g_h[N_ORIG * DD + i];
}

// ---------------- launch ----------------
extern "C" void kernel_launch(void* const* d_in, const int* in_sizes, int n_in,
                              void* d_out, int out_size)
{
    const float* x      = (const float*)d_in[0];
    const int*   sp     = (const int*)  d_in[1];
    const int*   bid    = (const int*)  d_in[2];
    const int*   deg    = (const int*)  d_in[3];
    const float* init_W = (const float*)d_in[4];
    const float* init_b = (const float*)d_in[5];
    const float* cent   = (const float*)d_in[6];
    const float* db     = (const float*)d_in[7];
    const float* vb     = (const float*)d_in[8];
    const float* Wq     = (const float*)d_in[9];
    const float* bq     = (const float*)d_in[10];
    const float* Wk     = (const float*)d_in[11];
    const float* bk     = (const float*)d_in[12];
    const float* Wv     = (const float*)d_in[13];
    const float* bv     = (const float*)d_in[14];
    const float* Wo     = (const float*)d_in[15];
    const float* bo     = (const float*)d_in[16];
    const float* W1     = (const float*)d_in[17];
    const float* b1     = (const float*)d_in[18];
    const float* W2     = (const float*)d_in[19];
    const float* b2     = (const float*)d_in[20];

    float *B, *h, *hn, *Q, *K, *V, *attn, *scores, *ff;
    cudaGetSymbolAddress((void**)&B,      g_B);
    cudaGetSymbolAddress((void**)&h,      g_h);
    cudaGetSymbolAddress((void**)&hn,     g_hn);
    cudaGetSymbolAddress((void**)&Q,      g_Q);
    cudaGetSymbolAddress((void**)&K,      g_K);
    cudaGetSymbolAddress((void**)&V,      g_V);
    cudaGetSymbolAddress((void**)&attn,   g_attn);
    cudaGetSymbolAddress((void**)&scores, g_scores);
    cudaGetSymbolAddress((void**)&ff,     g_ff);

    // B matrix (bias + mask)
    build_B_kernel<<<(NN * NN) / 256, 256>>>(sp, bid, db, vb);
    // init h
    init_h_kernel<<<(NN * DD) / 256, 256>>>(x, init_W, init_b, cent, deg);

    const float scale = 1.f / sqrtf((float)DKH);

    for (int l = 0; l < NL; l++) {
        // ---- attention ----
        ln_kernel<<<NN, 256>>>(h, hn);

        // QKV: per-head GEMM [2048,512]x[512,64], output packed [N, H*DK]
        {
            dim3 grid(1, NN / 64, NH);
            long long sB = (long long)DD * DKH, sBias = DKH, sC = DKH;
            gemm_nn<false, false><<<grid, 256>>>(hn, Wq + (size_t)l * NH * DD * DKH,
                bq + (size_t)l * NH * DKH, nullptr, Q,
                NN, DKH, DD, DD, DKH, DD, 0, sB, sBias, sC);
            gemm_nn<false, false><<<grid, 256>>>(hn, Wk + (size_t)l * NH * DD * DKH,
                bk + (size_t)l * NH * DKH, nullptr, K,
                NN, DKH, DD, DD, DKH, DD, 0, sB, sBias, sC);
            gemm_nn<false, false><<<grid, 256>>>(hn, Wv + (size_t)l * NH * DD * DKH,
                bv + (size_t)l * NH * DKH, nullptr, V,
                NN, DKH, DD, DD, DKH, DD, 0, sB, sBias, sC);
        }

        // logits = scale * Q K^T + B(mask)
        {
            dim3 grid(NN / 64, NN / 64, NH);
            gemm_nt_bias2d<<<grid, 256>>>(Q, K, B, scores,
                NN, NN, DKH, DD, DD, NN, NN,
                64LL, 64LL, (long long)NN * NN, scale);
        }

        // softmax rows
        softmax_kernel<<<NH * NN, 256>>>(scores);

        // attn_out = W * V   (packed [N, H*DK])
        {
            dim3 grid(1, NN / 64, NH);
            gemm_nn<false, false><<<grid, 256>>>(scores, V, nullptr, nullptr, attn,
                NN, DKH, NN, NN, DD, DD,
                (long long)NN * NN, 64LL, 0, 64LL);
        }

        // h = attn @ Wo + bo + h
        {
            dim3 grid(DD / 64, NN / 64, 1);
            gemm_nn<false, true><<<grid, 256>>>(attn, Wo + (size_t)l * DD * DD,
                bo + (size_t)l * DD, h, h,
                NN, DD, DD, DD, DD, DD, 0, 0, 0, 0);
        }

        // ---- FFN ----
        ln_kernel<<<NN, 256>>>(h, hn);
        {
            dim3 grid(FF / 64, NN / 64, 1);
            gemm_nn<true, false><<<grid, 256>>>(hn, W1 + (size_t)l * DD * FF,
                b1 + (size_t)l * FF, nullptr, ff,
                NN, FF, DD, DD, FF, FF, 0, 0, 0, 0);
        }
        {
            dim3 grid(DD / 64, NN / 64, 1);
            gemm_nn<false, true><<<grid, 256>>>(ff, W2 + (size_t)l * FF * DD,
                b2 + (size_t)l * DD, h, h,
                NN, DD, FF, FF, DD, DD, 0, 0, 0, 0);
        }
    }

    copy_out_kernel<<<(NG * DD) / 256, 256>>>((float*)d_out);
}

// round 4
// speedup vs baseline: 2.5546x; 2.5482x over previous
#include <cuda_runtime.h>
#include <math.h>
#include <stdint.h>

#define NG      64
#define N_ORIG  1984
#define NN      2048
#define DD      512
#define NH      8
#define DKH     64
#define FFD     2048
#define NL      4
#define NFE     32
#define MAX_SP  100
#define MAX_DEG 100

// ---------- scratch ----------
__device__ float g_B[(size_t)NN * NN];
__device__ float g_scores[(size_t)NH * NN * NN];
__device__ float g_ff[(size_t)NN * FFD];
__device__ float g_h[NN * DD];
__device__ float g_hn[NN * DD];
__device__ float g_Q[NN * DD];
__device__ float g_K[NN * DD];
__device__ float g_V[NN * DD];
__device__ float g_Vt[NN * DD];
__device__ float g_attn[NN * DD];
__device__ float g_WqT[NL * DD * DD];
__device__ float g_WkT[NL * DD * DD];
__device__ float g_WvT[NL * DD * DD];
__device__ float g_WoT[NL * DD * DD];
__device__ float g_W1T[NL * DD * FFD];
__device__ float g_W2T[NL * FFD * DD];

// ---------- helpers ----------
__device__ __forceinline__ uint32_t smem_u32(const void* p) {
    uint32_t a;
    asm("{ .reg .u64 t; cvta.to.shared.u64 t, %1; cvt.u32.u64 %0, t; }" : "=r"(a) : "l"(p));
    return a;
}
__device__ __forceinline__ float rnd_tf32(float x) {
    uint32_t r; asm("cvt.rna.tf32.f32 %0, %1;" : "=r"(r) : "f"(x));
    return __uint_as_float(r);
}
__device__ __forceinline__ void cp_async16(uint32_t d, const void* g) {
    asm volatile("cp.async.cg.shared.global [%0], [%1], 16;" :: "r"(d), "l"(g));
}
__device__ __forceinline__ void cp_commit() { asm volatile("cp.async.commit_group;" ::: "memory"); }
__device__ __forceinline__ void cp_wait1()  { asm volatile("cp.async.wait_group 1;"  ::: "memory"); }
__device__ __forceinline__ void cp_wait0()  { asm volatile("cp.async.wait_group 0;"  ::: "memory"); }

__device__ __forceinline__ uint32_t lds32(uint32_t addr) {
    uint32_t v; asm volatile("ld.shared.b32 %0, [%1];" : "=r"(v) : "r"(addr));
    return v;
}
// swizzled [row][32 floats] tile: byte = (row*128 + k*4) ^ ((row&7)<<4)
__device__ __forceinline__ uint32_t tile_addr(uint32_t base, int row, int k) {
    return base + ((((uint32_t)row << 7) + ((uint32_t)k << 2)) ^ (((uint32_t)row & 7u) << 4));
}

__device__ __forceinline__ void mma8(float* c, const uint32_t* a, const uint32_t* b) {
    asm volatile(
        "mma.sync.aligned.m16n8k8.row.col.f32.tf32.tf32.f32 "
        "{%0,%1,%2,%3}, {%4,%5,%6,%7}, {%8,%9}, {%0,%1,%2,%3};"
        : "+f"(c[0]), "+f"(c[1]), "+f"(c[2]), "+f"(c[3])
        : "r"(a[0]), "r"(a[1]), "r"(a[2]), "r"(a[3]), "r"(b[0]), "r"(b[1]));
}

// ---------- small kernels ----------
__global__ void build_B_kernel(const int* __restrict__ sp, const int* __restrict__ bid,
                               const float* __restrict__ db, const float* __restrict__ vb)
{
    size_t idx = (size_t)blockIdx.x * blockDim.x + threadIdx.x;
    if (idx >= (size_t)NN * NN) return;
    int i = (int)(idx / NN), j = (int)(idx % NN);
    float v;
    if (bid[i] != bid[j])      v = -INFINITY;
    else if (i == j)           v = db[0];
    else {
        bool vi = i >= N_ORIG, vj = j >= N_ORIG;
        if (vi != vj)          v = vb[0];
        else if (!vi)          v = db[min(sp[(size_t)i * N_ORIG + j], MAX_SP)];
        else                   v = db[MAX_SP + 1];
    }
    g_B[idx] = v;
}

__global__ void init_h_kernel(const float* __restrict__ x, const float* __restrict__ W,
                              const float* __restrict__ b, const float* __restrict__ cent,
                              const int* __restrict__ deg)
{
    int idx = blockIdx.x * blockDim.x + threadIdx.x;
    if (idx >= NN * DD) return;
    int n = idx / DD, d = idx % DD;
    float v = 0.f;
    if (n < N_ORIG) {
        v = b[d];
        #pragma unroll
        for (int f = 0; f < NFE; f++) v += x[n * NFE + f] * W[f * DD + d];
    }
    g_h[idx] = v + cent[min(deg[n], MAX_DEG) * DD + d];
}

__global__ void ln_kernel(const float* __restrict__ in, float* __restrict__ out)
{
    __shared__ float s1[256], s2[256];
    int row = blockIdx.x, t = threadIdx.x;
    const float* p = in + (size_t)row * DD;
    float a = 0.f, q = 0.f;
    for (int j = t; j < DD; j += 256) { float v = p[j]; a += v; q += v * v; }
    s1[t] = a; s2[t] = q; __syncthreads();
    for (int s = 128; s > 0; s >>= 1) {
        if (t < s) { s1[t] += s1[t + s]; s2[t] += s2[t + s]; }
        __syncthreads();
    }
    float mean = s1[0] * (1.f / DD);
    float var  = s2[0] * (1.f / DD) - mean * mean;
    float r = rsqrtf(var + 1e-5f);
    float* o = out + (size_t)row * DD;
    for (int j = t; j < DD; j += 256) o[j] = rnd_tf32((p[j] - mean) * r);
}

__global__ void softmax_rnd(float* __restrict__ S)
{
    __shared__ float red[8];
    float* p = S + (size_t)blockIdx.x * NN;
    int t = threadIdx.x, lane = t & 31, w = t >> 5;
    float v[8];
    #pragma unroll
    for (int j = 0; j < 8; j++) v[j] = p[j * 256 + t];
    float m = v[0];
    #pragma unroll
    for (int j = 1; j < 8; j++) m = fmaxf(m, v[j]);
    #pragma unroll
    for (int o = 16; o; o >>= 1) m = fmaxf(m, __shfl_xor_sync(~0u, m, o));
    if (lane == 0) red[w] = m;
    __syncthreads();
    m = red[0];
    #pragma unroll
    for (int j = 1; j < 8; j++) m = fmaxf(m, red[j]);
    float sum = 0.f;
    #pragma unroll
    for (int j = 0; j < 8; j++) { v[j] = __expf(v[j] - m); sum += v[j]; }
    #pragma unroll
    for (int o = 16; o; o >>= 1) sum += __shfl_xor_sync(~0u, sum, o);
    __syncthreads();
    if (lane == 0) red[w] = sum;
    __syncthreads();
    sum = red[0] + red[1] + red[2] + red[3] + red[4] + red[5] + red[6] + red[7];
    float inv = 1.f / sum;
    #pragma unroll
    for (int j = 0; j < 8; j++) p[j * 256 + t] = rnd_tf32(v[j] * inv);
}

// out[z][C][R] = rnd(in[z][R][C]); grid (C/32, R/32, batch), block (32,8)
__global__ void transpose_rnd(const float* __restrict__ in, float* __restrict__ out, int R, int C)
{
    __shared__ float t[32][33];
    size_t zoff = (size_t)blockIdx.z * R * C;
    in += zoff; out += zoff;
    int c0 = blockIdx.x * 32, r0 = blockIdx.y * 32;
    for (int i = threadIdx.y; i < 32; i += 8)
        t[i][threadIdx.x] = in[(size_t)(r0 + i) * C + c0 + threadIdx.x];
    __syncthreads();
    for (int i = threadIdx.y; i < 32; i += 8)
        out[(size_t)(c0 + i) * R + r0 + threadIdx.x] = rnd_tf32(t[threadIdx.x][i]);
}

__global__ void copy_out_kernel(float* __restrict__ out)
{
    int i = blockIdx.x * blockDim.x + threadIdx.x;
    if (i < NG * DD) out[i] = g_h[N_ORIG * DD + i];
}

// ---------- staging: 128xTN chunk of 32 K-floats, swizzled ----------
template<int TN>
__device__ __forceinline__ void load_tiles(const float* A, int lda, const float* Bt, int ldb,
        int row0, int col0, int k0, uint32_t aS, uint32_t bS, int tid)
{
    #pragma unroll
    for (int i = 0; i < 4; i++) {
        int u = tid + i * 256;
        int r = u >> 3, q = u & 7;
        uint32_t off = ((uint32_t)u << 4) ^ (((uint32_t)(r & 7)) << 4);
        cp_async16(aS + off, A + (size_t)(row0 + r) * lda + k0 + q * 4);
    }
    #pragma unroll
    for (int i = 0; i < TN / 32; i++) {
        int u = tid + i * 256;
        int r = u >> 3, q = u & 7;
        uint32_t off = ((uint32_t)u << 4) ^ (((uint32_t)(r & 7)) << 4);
        cp_async16(bS + off, Bt + (size_t)(col0 + r) * ldb + k0 + q * 4);
    }
}

// ---------- tf32 mma.sync NT GEMM: C[128,TN] = A[.,K] x Bt[.,K]^T + epilogue ----------
// MODE 0: rnd | 1: rnd(+bias[c]) | 2: *scale + bias2d[r][c] | 3: +bias[c]+res[r][c] | 4: rnd(relu(+bias[c]))
template<int TN, int MODE>
__global__ void __launch_bounds__(256)
gemm_mma(const float* __restrict__ A, int lda, long long aZ,
         const float* __restrict__ Bt, int ldb, long long bZ,
         float* __restrict__ C, int ldc, long long cZ,
         int K,
         const float* __restrict__ bias,
         const float* __restrict__ res,
         const float* __restrict__ bias2d, int ldb2, float scale)
{
    constexpr int WC = TN / 64;       // warps across cols
    constexpr int WR = 8 / WC;        // warps across rows
    constexpr int WROWS = 128 / WR;   // 32 or 16
    constexpr int MT = WROWS / 16;    // m16 tiles per warp

    extern __shared__ char smraw[];
    uint32_t rawu = smem_u32(smraw);
    uint32_t base = (rawu + 127u) & ~127u;

    const int tid = threadIdx.x;
    const int z = blockIdx.z;
    A  += (size_t)z * aZ;
    Bt += (size_t)z * bZ;
    C  += (size_t)z * cZ;

    const int col0 = blockIdx.x * TN;
    const int row0 = blockIdx.y * 128;

    uint32_t aS[2] = { base, base + 128u * 32u * 4u };
    uint32_t bS[2] = { base + 2u * 128u * 32u * 4u,
                       base + 2u * 128u * 32u * 4u + (uint32_t)TN * 32u * 4u };

    const int w = tid >> 5, lane = tid & 31;
    const int wr = w / WC, wc = w % WC;
    const int g = lane >> 2, cq = lane & 3;

    float acc[MT][8][4];
    #pragma unroll
    for (int mt = 0; mt < MT; mt++)
        #pragma unroll
        for (int nt = 0; nt < 8; nt++)
            #pragma unroll
            for (int i = 0; i < 4; i++) acc[mt][nt][i] = 0.f;

    const int nc = K >> 5;
    load_tiles<TN>(A, lda, Bt, ldb, row0, col0, 0, aS[0], bS[0], tid);
    cp_commit();

    for (int cch = 0; cch < nc; cch++) {
        int s = cch & 1;
        if (cch + 1 < nc) {
            load_tiles<TN>(A, lda, Bt, ldb, row0, col0, (cch + 1) << 5, aS[s ^ 1], bS[s ^ 1], tid);
            cp_commit();
            cp_wait1();
        } else {
            cp_wait0();
        }
        __syncthreads();
        #pragma unroll
        for (int kk = 0; kk < 4; kk++) {
            const int k0 = kk * 8;
            uint32_t afr[MT][4];
            #pragma unroll
            for (int mt = 0; mt < MT; mt++) {
                int rb = wr * WROWS + mt * 16 + g;
                afr[mt][0] = lds32(tile_addr(aS[s], rb,     k0 + cq));
                afr[mt][1] = lds32(tile_addr(aS[s], rb + 8, k0 + cq));
                afr[mt][2] = lds32(tile_addr(aS[s], rb,     k0 + cq + 4));
                afr[mt][3] = lds32(tile_addr(aS[s], rb + 8, k0 + cq + 4));
            }
            uint32_t bfr[8][2];
            #pragma unroll
            for (int nt = 0; nt < 8; nt++) {
                int nb = wc * 64 + nt * 8 + g;
                bfr[nt][0] = lds32(tile_addr(bS[s], nb, k0 + cq));
                bfr[nt][1] = lds32(tile_addr(bS[s], nb, k0 + cq + 4));
            }
            #pragma unroll
            for (int mt = 0; mt < MT; mt++)
                #pragma unroll
                for (int nt = 0; nt < 8; nt++)
                    mma8(acc[mt][nt], afr[mt], bfr[nt]);
        }
        __syncthreads();
    }

    // epilogue: each thread owns pairs (r, c..c+1)
    #pragma unroll
    for (int mt = 0; mt < MT; mt++) {
        #pragma unroll
        for (int nt = 0; nt < 8; nt++) {
            int cc = col0 + wc * 64 + nt * 8 + cq * 2;
            #pragma unroll
            for (int half = 0; half < 2; half++) {
                int r = row0 + wr * WROWS + mt * 16 + g + half * 8;
                float v0 = acc[mt][nt][half * 2];
                float v1 = acc[mt][nt][half * 2 + 1];
                if (MODE == 1 || MODE == 3 || MODE == 4) { v0 += bias[cc]; v1 += bias[cc + 1]; }
                if (MODE == 2) {
                    v0 = v0 * scale + bias2d[(size_t)r * ldb2 + cc];
                    v1 = v1 * scale + bias2d[(size_t)r * ldb2 + cc + 1];
                }
                if (MODE == 3) {
                    v0 += res[(size_t)r * ldc + cc];
                    v1 += res[(size_t)r * ldc + cc + 1];
                }
                if (MODE == 4) { v0 = fmaxf(v0, 0.f); v1 = fmaxf(v1, 0.f); }
                if (MODE == 0 || MODE == 1 || MODE == 4) { v0 = rnd_tf32(v0); v1 = rnd_tf32(v1); }
                float2 o; o.x = v0; o.y = v1;
                *(float2*)(C + (size_t)r * ldc + cc) = o;
            }
        }
    }
}

// ---------- launch ----------
static inline int smbytes(int tn) { return 128 + (128 * 32 * 2 + tn * 32 * 2) * 4; }

extern "C" void kernel_launch(void* const* d_in, const int* in_sizes, int n_in,
                              void* d_out, int out_size)
{
    const float* x      = (const float*)d_in[0];
    const int*   sp     = (const int*)  d_in[1];
    const int*   bid    = (const int*)  d_in[2];
    const int*   deg    = (const int*)  d_in[3];
    const float* init_W = (const float*)d_in[4];
    const float* init_b = (const float*)d_in[5];
    const float* cent   = (const float*)d_in[6];
    const float* db     = (const float*)d_in[7];
    const float* vb     = (const float*)d_in[8];
    const float* Wq     = (const float*)d_in[9];
    const float* bq     = (const float*)d_in[10];
    const float* Wk     = (const float*)d_in[11];
    const float* bk     = (const float*)d_in[12];
    const float* Wv     = (const float*)d_in[13];
    const float* bv     = (const float*)d_in[14];
    const float* Wo     = (const float*)d_in[15];
    const float* bo     = (const float*)d_in[16];
    const float* W1     = (const float*)d_in[17];
    const float* b1     = (const float*)d_in[18];
    const float* W2     = (const float*)d_in[19];
    const float* b2     = (const float*)d_in[20];

    float *Bm, *h, *hn, *Q, *K_, *V, *Vt, *attn, *scores, *ff;
    float *WqT, *WkT, *WvT, *WoT, *W1T, *W2T;
    cudaGetSymbolAddress((void**)&Bm, g_B);
    cudaGetSymbolAddress((void**)&h, g_h);
    cudaGetSymbolAddress((void**)&hn, g_hn);
    cudaGetSymbolAddress((void**)&Q, g_Q);
    cudaGetSymbolAddress((void**)&K_, g_K);
    cudaGetSymbolAddress((void**)&V, g_V);
    cudaGetSymbolAddress((void**)&Vt, g_Vt);
    cudaGetSymbolAddress((void**)&attn, g_attn);
    cudaGetSymbolAddress((void**)&scores, g_scores);
    cudaGetSymbolAddress((void**)&ff, g_ff);
    cudaGetSymbolAddress((void**)&WqT, g_WqT);
    cudaGetSymbolAddress((void**)&WkT, g_WkT);
    cudaGetSymbolAddress((void**)&WvT, g_WvT);
    cudaGetSymbolAddress((void**)&WoT, g_WoT);
    cudaGetSymbolAddress((void**)&W1T, g_W1T);
    cudaGetSymbolAddress((void**)&W2T, g_W2T);

    cudaFuncSetAttribute(gemm_mma<128, 1>, cudaFuncAttributeMaxDynamicSharedMemorySize, smbytes(128));
    cudaFuncSetAttribute(gemm_mma<128, 2>, cudaFuncAttributeMaxDynamicSharedMemorySize, smbytes(128));
    cudaFuncSetAttribute(gemm_mma<128, 3>, cudaFuncAttributeMaxDynamicSharedMemorySize, smbytes(128));
    cudaFuncSetAttribute(gemm_mma<128, 4>, cudaFuncAttributeMaxDynamicSharedMemorySize, smbytes(128));
    cudaFuncSetAttribute(gemm_mma<64, 0>,  cudaFuncAttributeMaxDynamicSharedMemorySize, smbytes(64));

    // weight transposes (+ tf32 rounding). WxT[h*64+k][d] = big NT operand.
    {
        dim3 blk(32, 8);
        transpose_rnd<<<dim3(2, 16, NL * NH), blk>>>(Wq, WqT, DD, DKH);
        transpose_rnd<<<dim3(2, 16, NL * NH), blk>>>(Wk, WkT, DD, DKH);
        transpose_rnd<<<dim3(2, 16, NL * NH), blk>>>(Wv, WvT, DD, DKH);
        transpose_rnd<<<dim3(16, 16, NL), blk>>>(Wo, WoT, DD, DD);
        transpose_rnd<<<dim3(64, 16, NL), blk>>>(W1, W1T, DD, FFD);
        transpose_rnd<<<dim3(16, 64, NL), blk>>>(W2, W2T, FFD, DD);
    }

    build_B_kernel<<<(NN * NN) / 256, 256>>>(sp, bid, db, vb);
    init_h_kernel<<<(NN * DD) / 256, 256>>>(x, init_W, init_b, cent, deg);

    const float scale = 1.f / sqrtf((float)DKH);

    for (int l = 0; l < NL; l++) {
        ln_kernel<<<NN, 256>>>(h, hn);

        // QKV: [2048,512] = hn x WT(512x512)
        {
            dim3 grid(DD / 128, NN / 128, 1);
            gemm_mma<128, 1><<<grid, 256, smbytes(128)>>>(hn, DD, 0,
                WqT + (size_t)l * DD * DD, DD, 0, Q, DD, 0, DD,
                bq + (size_t)l * DD, nullptr, nullptr, 0, 0.f);
            gemm_mma<128, 1><<<grid, 256, smbytes(128)>>>(hn, DD, 0,
                WkT + (size_t)l * DD * DD, DD, 0, K_, DD, 0, DD,
                bk + (size_t)l * DD, nullptr, nullptr, 0, 0.f);
            gemm_mma<128, 1><<<grid, 256, smbytes(128)>>>(hn, DD, 0,
                WvT + (size_t)l * DD * DD, DD, 0, V, DD, 0, DD,
                bv + (size_t)l * DD, nullptr, nullptr, 0, 0.f);
        }

        // logits = scale * Q K^T + B   (per head)
        {
            dim3 grid(NN / 128, NN / 128, NH);
            gemm_mma<128, 2><<<grid, 256, smbytes(128)>>>(Q, DD, DKH, K_, DD, DKH,
                scores, NN, (long long)NN * NN, DKH,
                nullptr, nullptr, Bm, NN, scale);
        }

        softmax_rnd<<<NH * NN, 256>>>(scores);

        // Vt = V^T  [512][2048]
        transpose_rnd<<<dim3(DD / 32, NN / 32, 1), dim3(32, 8)>>>(V, Vt, NN, DD);

        // attn = softmax(scores) @ V   (per head, TN=64)
        {
            dim3 grid(1, NN / 128, NH);
            gemm_mma<64, 0><<<grid, 256, smbytes(64)>>>(scores, NN, (long long)NN * NN,
                Vt, NN, (long long)DKH * NN,
                attn, DD, DKH, NN, nullptr, nullptr, nullptr, 0, 0.f);
        }

        // h = attn @ Wo + bo + h
        {
            dim3 grid(DD / 128, NN / 128, 1);
            gemm_mma<128, 3><<<grid, 256, smbytes(128)>>>(attn, DD, 0,
                WoT + (size_t)l * DD * DD, DD, 0, h, DD, 0, DD,
                bo + (size_t)l * DD, h, nullptr, 0, 0.f);
        }

        ln_kernel<<<NN, 256>>>(h, hn);

        // ff = relu(hn @ W1 + b1)
        {
            dim3 grid(FFD / 128, NN / 128, 1);
            gemm_mma<128, 4><<<grid, 256, smbytes(128)>>>(hn, DD, 0,
                W1T + (size_t)l * DD * FFD, DD, 0, ff, FFD, 0, DD,
                b1 + (size_t)l * FFD, nullptr, nullptr, 0, 0.f);
        }
        // h = ff @ W2 + b2 + h
        {
            dim3 grid(DD / 128, NN / 128, 1);
            gemm_mma<128, 3><<<grid, 256, smbytes(128)>>>(ff, FFD, 0,
                W2T + (size_t)l * FFD * DD, FFD, 0, h, DD, 0, FFD,
                b2 + (size_t)l * DD, h, nullptr, 0, 0.f);
        }
    }

    copy_out_kernel<<<(NG * DD) / 256, 256>>>((float*)d_out);
}

// round 5
// speedup vs baseline: 5.6191x; 2.1996x over previous
#include <cuda_runtime.h>
#include <math.h>
#include <stdint.h>

#define NG      64
#define N_ORIG  1984
#define NN      2048
#define DD      512
#define NH      8
#define DKH     64
#define FFD     2048
#define NL      4
#define NFE     32
#define MAX_SP  100
#define MAX_DEG 100
#define QKVW    1536   // packed q|k|v width

// ---------- scratch ----------
__device__ float g_h[NN * DD];
__device__ float g_hn[NN * DD];
__device__ float g_qkv[NN * QKVW];
__device__ float g_attn[NN * DD];
__device__ float g_ff[(size_t)NN * FFD];
__device__ float g_WqkvT[NL * QKVW * DD];
__device__ float g_bqkv[NL * QKVW];
__device__ float g_WoT[NL * DD * DD];
__device__ float g_W1T[NL * DD * FFD];
__device__ float g_W2T[NL * FFD * DD];

// ---------- helpers ----------
__device__ __forceinline__ uint32_t smem_u32(const void* p) {
    uint32_t a;
    asm("{ .reg .u64 t; cvta.to.shared.u64 t, %1; cvt.u32.u64 %0, t; }" : "=r"(a) : "l"(p));
    return a;
}
__device__ __forceinline__ float rnd_tf32(float x) {
    uint32_t r; asm("cvt.rna.tf32.f32 %0, %1;" : "=r"(r) : "f"(x));
    return __uint_as_float(r);
}
__device__ __forceinline__ void cp_async16(uint32_t d, const void* g) {
    asm volatile("cp.async.cg.shared.global [%0], [%1], 16;" :: "r"(d), "l"(g));
}
__device__ __forceinline__ void cp_commit() { asm volatile("cp.async.commit_group;" ::: "memory"); }
__device__ __forceinline__ void cp_wait1()  { asm volatile("cp.async.wait_group 1;"  ::: "memory"); }
__device__ __forceinline__ void cp_wait0()  { asm volatile("cp.async.wait_group 0;"  ::: "memory"); }
__device__ __forceinline__ uint32_t lds32(uint32_t addr) {
    uint32_t v; asm volatile("ld.shared.b32 %0, [%1];" : "=r"(v) : "r"(addr));
    return v;
}
__device__ __forceinline__ uint32_t tile_addr(uint32_t base, int row, int k) {
    return base + ((((uint32_t)row << 7) + ((uint32_t)k << 2)) ^ (((uint32_t)row & 7u) << 4));
}
__device__ __forceinline__ void mma8(float* c, const uint32_t* a, const uint32_t* b) {
    asm volatile(
        "mma.sync.aligned.m16n8k8.row.col.f32.tf32.tf32.f32 "
        "{%0,%1,%2,%3}, {%4,%5,%6,%7}, {%8,%9}, {%0,%1,%2,%3};"
        : "+f"(c[0]), "+f"(c[1]), "+f"(c[2]), "+f"(c[3])
        : "r"(a[0]), "r"(a[1]), "r"(a[2]), "r"(a[3]), "r"(b[0]), "r"(b[1]));
}

// ---------- small kernels ----------
__global__ void init_h_kernel(const float* __restrict__ x, const float* __restrict__ W,
                              const float* __restrict__ b, const float* __restrict__ cent,
                              const int* __restrict__ deg)
{
    int idx = blockIdx.x * blockDim.x + threadIdx.x;
    if (idx >= NN * DD) return;
    int n = idx / DD, d = idx % DD;
    float v = 0.f;
    if (n < N_ORIG) {
        v = b[d];
        #pragma unroll
        for (int f = 0; f < NFE; f++) v += x[n * NFE + f] * W[f * DD + d];
    }
    g_h[idx] = v + cent[min(deg[n], MAX_DEG) * DD + d];
}

__global__ void ln_kernel(const float* __restrict__ in, float* __restrict__ out)
{
    __shared__ float s1[256], s2[256];
    int row = blockIdx.x, t = threadIdx.x;
    const float* p = in + (size_t)row * DD;
    float a = 0.f, q = 0.f;
    for (int j = t; j < DD; j += 256) { float v = p[j]; a += v; q += v * v; }
    s1[t] = a; s2[t] = q; __syncthreads();
    for (int s = 128; s > 0; s >>= 1) {
        if (t < s) { s1[t] += s1[t + s]; s2[t] += s2[t + s]; }
        __syncthreads();
    }
    float mean = s1[0] * (1.f / DD);
    float var  = s2[0] * (1.f / DD) - mean * mean;
    float r = rsqrtf(var + 1e-5f);
    float* o = out + (size_t)row * DD;
    for (int j = t; j < DD; j += 256) o[j] = rnd_tf32((p[j] - mean) * r);
}

// generic transpose+rnd: out[z][C][R] = rnd(in[z][R][C])
__global__ void transpose_rnd(const float* __restrict__ in, float* __restrict__ out, int R, int C)
{
    __shared__ float t[32][33];
    size_t zoff = (size_t)blockIdx.z * R * C;
    in += zoff; out += zoff;
    int c0 = blockIdx.x * 32, r0 = blockIdx.y * 32;
    for (int i = threadIdx.y; i < 32; i += 8)
        t[i][threadIdx.x] = in[(size_t)(r0 + i) * C + c0 + threadIdx.x];
    __syncthreads();
    for (int i = threadIdx.y; i < 32; i += 8)
        out[(size_t)(c0 + i) * R + r0 + threadIdx.x] = rnd_tf32(t[threadIdx.x][i]);
}

// pack Wq/Wk/Wv -> WqkvT[l][qkv*512 + h*64 + k][d] (transposed + rnd)
// grid (DKH/32=2, DD/32=16, NL*3*NH), block (32,8)
__global__ void pack_qkvT(const float* __restrict__ Wq, const float* __restrict__ Wk,
                          const float* __restrict__ Wv, float* __restrict__ out)
{
    __shared__ float t[32][33];
    int z = blockIdx.z;
    int h = z & 7, qkv = (z >> 3) % 3, l = z / 24;
    const float* src = (qkv == 0 ? Wq : qkv == 1 ? Wk : Wv) + (size_t)(l * NH + h) * DD * DKH;
    float* dst = out + (size_t)l * QKVW * DD + (size_t)(qkv * DD + h * DKH) * DD;
    int c0 = blockIdx.x * 32, r0 = blockIdx.y * 32;   // c over DKH, r over DD
    for (int i = threadIdx.y; i < 32; i += 8)
        t[i][threadIdx.x] = src[(size_t)(r0 + i) * DKH + c0 + threadIdx.x];
    __syncthreads();
    for (int i = threadIdx.y; i < 32; i += 8)
        dst[(size_t)(c0 + i) * DD + r0 + threadIdx.x] = rnd_tf32(t[threadIdx.x][i]);
}

__global__ void pack_bias(const float* __restrict__ bq, const float* __restrict__ bk,
                          const float* __restrict__ bv, float* __restrict__ out)
{
    int idx = blockIdx.x * blockDim.x + threadIdx.x;
    if (idx >= NL * QKVW) return;
    int l = idx / QKVW, p = idx % QKVW;
    float v;
    if (p < DD)            v = bq[l * DD + p];
    else if (p < 2 * DD)   v = bk[l * DD + p - DD];
    else                   v = bv[l * DD + p - 2 * DD];
    out[idx] = v;
}

__global__ void copy_out_kernel(float* __restrict__ out)
{
    int i = blockIdx.x * blockDim.x + threadIdx.x;
    if (i < NG * DD) out[i] = g_h[N_ORIG * DD + i];
}

// ---------- fused block-diagonal attention ----------
// grid (NG, 2), block 128. warp w handles head h = blockIdx.y*4 + w of graph g.
// qkv packed rows [NN][1536]: q|k|v. Output attn[NN][512], tf32-rounded.
__global__ void __launch_bounds__(128)
attn_fused(const float* __restrict__ qkv, float* __restrict__ O,
           const int* __restrict__ sp, const float* __restrict__ db,
           const float* __restrict__ vb, float scale)
{
    extern __shared__ float sm[];
    // layout (floats): Ks[4][2048] | Ps[4][1056] | Bs[1056]
    const int g = blockIdx.x;
    const int w = threadIdx.x >> 5, lane = threadIdx.x & 31;
    const int h = blockIdx.y * 4 + w;
    float* Ks = sm + w * 2048;
    float* Ps = sm + 4 * 2048 + w * 1056;
    float* Bs = sm + 4 * 2048 + 4 * 1056;

    // Bs: bias block for this graph (shared by all heads)
    for (int t = threadIdx.x; t < 32 * 32; t += 128) {
        int r = t >> 5, c = t & 31;
        int i = (r < 31) ? g * 31 + r : N_ORIG + g;
        int j = (c < 31) ? g * 31 + c : N_ORIG + g;
        float bvv;
        if (i == j)                     bvv = db[0];
        else if ((r == 31) != (c == 31)) bvv = vb[0];
        else                            bvv = db[min(sp[(size_t)i * N_ORIG + j], MAX_SP)];
        Bs[r * 33 + c] = bvv;
    }
    __syncthreads();

    // load K head-slice into smem: Ks[c][k] = K[n(c)][h*64+k]
    for (int t = lane; t < 512; t += 32) {   // 512 float4 = 32 rows x 16
        int c = t >> 4, kq = t & 15;
        int n = (c < 31) ? g * 31 + c : N_ORIG + g;
        const float4 v4 = *(const float4*)(qkv + (size_t)n * QKVW + DD + h * DKH + kq * 4);
        *(float4*)(Ks + c * 64 + kq * 4) = v4;
    }
    __syncwarp();

    // q row (lane = query row r)
    const int r = lane;
    const int nr = (r < 31) ? g * 31 + r : N_ORIG + g;
    const float4* qp = (const float4*)(qkv + (size_t)nr * QKVW + h * DKH);
    float4 q[16];
    #pragma unroll
    for (int i = 0; i < 16; i++) q[i] = qp[i];

    // S row + per-lane softmax
    float s[32];
    #pragma unroll
    for (int c = 0; c < 32; c++) {
        const float2* kr = (const float2*)(Ks + c * 64);
        float acc = 0.f;
        #pragma unroll
        for (int i = 0; i < 16; i++) {
            float2 a = kr[2 * i], b = kr[2 * i + 1];
            acc += q[i].x * a.x + q[i].y * a.y + q[i].z * b.x + q[i].w * b.y;
        }
        s[c] = acc * scale + Bs[r * 33 + c];
    }
    float m = s[0];
    #pragma unroll
    for (int c = 1; c < 32; c++) m = fmaxf(m, s[c]);
    float sum = 0.f;
    #pragma unroll
    for (int c = 0; c < 32; c++) { s[c] = __expf(s[c] - m); sum += s[c]; }
    float inv = 1.f / sum;
    #pragma unroll
    for (int c = 0; c < 32; c++) Ps[r * 33 + c] = s[c] * inv;
    __syncwarp();

    // V columns into regs: lane owns cols (lane, lane+32)
    float va[32], vb2[32];
    #pragma unroll
    for (int c = 0; c < 32; c++) {
        int n = (c < 31) ? g * 31 + c : N_ORIG + g;
        const float* vp = qkv + (size_t)n * QKVW + 2 * DD + h * DKH;
        va[c]  = vp[lane];
        vb2[c] = vp[lane + 32];
    }

    // O[rr][d] = sum_c P[rr][c] * V[c][d]
    for (int rr = 0; rr < 32; rr++) {
        float a0 = 0.f, a1 = 0.f;
        #pragma unroll
        for (int c = 0; c < 32; c++) {
            float p = Ps[rr * 33 + c];
            a0 += p * va[c];
            a1 += p * vb2[c];
        }
        int n = (rr < 31) ? g * 31 + rr : N_ORIG + g;
        float* op = O + (size_t)n * DD + h * DKH;
        op[lane]      = rnd_tf32(a0);
        op[lane + 32] = rnd_tf32(a1);
    }
}

// ---------- staging for gemm ----------
template<int TN>
__device__ __forceinline__ void load_tiles(const float* A, int lda, const float* Bt, int ldb,
        int row0, int col0, int k0, uint32_t aS, uint32_t bS, int tid)
{
    #pragma unroll
    for (int i = 0; i < 4; i++) {
        int u = tid + i * 256;
        int r = u >> 3, q = u & 7;
        uint32_t off = ((uint32_t)u << 4) ^ (((uint32_t)(r & 7)) << 4);
        cp_async16(aS + off, A + (size_t)(row0 + r) * lda + k0 + q * 4);
    }
    #pragma unroll
    for (int i = 0; i < TN / 32; i++) {
        int u = tid + i * 256;
        int r = u >> 3, q = u & 7;
        uint32_t off = ((uint32_t)u << 4) ^ (((uint32_t)(r & 7)) << 4);
        cp_async16(bS + off, Bt + (size_t)(col0 + r) * ldb + k0 + q * 4);
    }
}

// ---------- tf32 mma.sync NT GEMM ----------
// MODE 3: +bias[c]+res[r][c] | 4: rnd(relu(+bias[c])) | 5: +bias[c] (no rnd)
template<int TN, int MODE>
__global__ void __launch_bounds__(256)
gemm_mma(const float* __restrict__ A, int lda,
         const float* __restrict__ Bt, int ldb,
         float* __restrict__ C, int ldc,
         int K,
         const float* __restrict__ bias,
         const float* __restrict__ res)
{
    constexpr int WC = TN / 64;
    constexpr int WR = 8 / WC;
    constexpr int WROWS = 128 / WR;
    constexpr int MT = WROWS / 16;

    extern __shared__ char smraw[];
    uint32_t rawu = smem_u32(smraw);
    uint32_t base = (rawu + 127u) & ~127u;

    const int tid = threadIdx.x;
    const int col0 = blockIdx.x * TN;
    const int row0 = blockIdx.y * 128;

    uint32_t aS[2] = { base, base + 128u * 32u * 4u };
    uint32_t bS[2] = { base + 2u * 128u * 32u * 4u,
                       base + 2u * 128u * 32u * 4u + (uint32_t)TN * 32u * 4u };

    const int w = tid >> 5, lane = tid & 31;
    const int wr = w / WC, wc = w % WC;
    const int g = lane >> 2, cq = lane & 3;

    float acc[MT][8][4];
    #pragma unroll
    for (int mt = 0; mt < MT; mt++)
        #pragma unroll
        for (int nt = 0; nt < 8; nt++)
            #pragma unroll
            for (int i = 0; i < 4; i++) acc[mt][nt][i] = 0.f;

    const int nc = K >> 5;
    load_tiles<TN>(A, lda, Bt, ldb, row0, col0, 0, aS[0], bS[0], tid);
    cp_commit();

    for (int cch = 0; cch < nc; cch++) {
        int s = cch & 1;
        if (cch + 1 < nc) {
            load_tiles<TN>(A, lda, Bt, ldb, row0, col0, (cch + 1) << 5, aS[s ^ 1], bS[s ^ 1], tid);
            cp_commit();
            cp_wait1();
        } else {
            cp_wait0();
        }
        __syncthreads();
        #pragma unroll
        for (int kk = 0; kk < 4; kk++) {
            const int k0 = kk * 8;
            uint32_t afr[MT][4];
            #pragma unroll
            for (int mt = 0; mt < MT; mt++) {
                int rb = wr * WROWS + mt * 16 + g;
                afr[mt][0] = lds32(tile_addr(aS[s], rb,     k0 + cq));
                afr[mt][1] = lds32(tile_addr(aS[s], rb + 8, k0 + cq));
                afr[mt][2] = lds32(tile_addr(aS[s], rb,     k0 + cq + 4));
                afr[mt][3] = lds32(tile_addr(aS[s], rb + 8, k0 + cq + 4));
            }
            uint32_t bfr[8][2];
            #pragma unroll
            for (int nt = 0; nt < 8; nt++) {
                int nb = wc * 64 + nt * 8 + g;
                bfr[nt][0] = lds32(tile_addr(bS[s], nb, k0 + cq));
                bfr[nt][1] = lds32(tile_addr(bS[s], nb, k0 + cq + 4));
            }
            #pragma unroll
            for (int mt = 0; mt < MT; mt++)
                #pragma unroll
                for (int nt = 0; nt < 8; nt++)
                    mma8(acc[mt][nt], afr[mt], bfr[nt]);
        }
        __syncthreads();
    }

    #pragma unroll
    for (int mt = 0; mt < MT; mt++) {
        #pragma unroll
        for (int nt = 0; nt < 8; nt++) {
            int cc = col0 + wc * 64 + nt * 8 + cq * 2;
            #pragma unroll
            for (int half = 0; half < 2; half++) {
                int r = row0 + wr * WROWS + mt * 16 + g + half * 8;
                float v0 = acc[mt][nt][half * 2];
                float v1 = acc[mt][nt][half * 2 + 1];
                v0 += bias[cc]; v1 += bias[cc + 1];
                if (MODE == 3) {
                    v0 += res[(size_t)r * ldc + cc];
                    v1 += res[(size_t)r * ldc + cc + 1];
                }
                if (MODE == 4) {
                    v0 = rnd_tf32(fmaxf(v0, 0.f));
                    v1 = rnd_tf32(fmaxf(v1, 0.f));
                }
                float2 o; o.x = v0; o.y = v1;
                *(float2*)(C + (size_t)r * ldc + cc) = o;
            }
        }
    }
}

// ---------- launch ----------
static inline int smbytes(int tn) { return 128 + (128 * 32 * 2 + tn * 32 * 2) * 4; }
#define ATTN_SMEM ((4 * 2048 + 4 * 1056 + 1056) * 4)

extern "C" void kernel_launch(void* const* d_in, const int* in_sizes, int n_in,
                              void* d_out, int out_size)
{
    const float* x      = (const float*)d_in[0];
    const int*   sp     = (const int*)  d_in[1];
    const int*   bid    = (const int*)  d_in[2]; (void)bid;
    const int*   deg    = (const int*)  d_in[3];
    const float* init_W = (const float*)d_in[4];
    const float* init_b = (const float*)d_in[5];
    const float* cent   = (const float*)d_in[6];
    const float* db     = (const float*)d_in[7];
    const float* vb     = (const float*)d_in[8];
    const float* Wq     = (const float*)d_in[9];
    const float* bq     = (const float*)d_in[10];
    const float* Wk     = (const float*)d_in[11];
    const float* bk     = (const float*)d_in[12];
    const float* Wv     = (const float*)d_in[13];
    const float* bv     = (const float*)d_in[14];
    const float* Wo     = (const float*)d_in[15];
    const float* bo     = (const float*)d_in[16];
    const float* W1     = (const float*)d_in[17];
    const float* b1     = (const float*)d_in[18];
    const float* W2     = (const float*)d_in[19];
    const float* b2     = (const float*)d_in[20];

    float *h, *hn, *qkv, *attn, *ff, *WqkvT, *bqkv, *WoT, *W1T, *W2T;
    cudaGetSymbolAddress((void**)&h, g_h);
    cudaGetSymbolAddress((void**)&hn, g_hn);
    cudaGetSymbolAddress((void**)&qkv, g_qkv);
    cudaGetSymbolAddress((void**)&attn, g_attn);
    cudaGetSymbolAddress((void**)&ff, g_ff);
    cudaGetSymbolAddress((void**)&WqkvT, g_WqkvT);
    cudaGetSymbolAddress((void**)&bqkv, g_bqkv);
    cudaGetSymbolAddress((void**)&WoT, g_WoT);
    cudaGetSymbolAddress((void**)&W1T, g_W1T);
    cudaGetSymbolAddress((void**)&W2T, g_W2T);

    cudaFuncSetAttribute(gemm_mma<128, 5>, cudaFuncAttributeMaxDynamicSharedMemorySize, smbytes(128));
    cudaFuncSetAttribute(gemm_mma<128, 4>, cudaFuncAttributeMaxDynamicSharedMemorySize, smbytes(128));
    cudaFuncSetAttribute(gemm_mma<64, 3>,  cudaFuncAttributeMaxDynamicSharedMemorySize, smbytes(64));
    cudaFuncSetAttribute(attn_fused, cudaFuncAttributeMaxDynamicSharedMemorySize, ATTN_SMEM);

    // pack weights (transpose + tf32 rounding)
    {
        dim3 blk(32, 8);
        pack_qkvT<<<dim3(2, 16, NL * 3 * NH), blk>>>(Wq, Wk, Wv, WqkvT);
        transpose_rnd<<<dim3(16, 16, NL), blk>>>(Wo, WoT, DD, DD);
        transpose_rnd<<<dim3(64, 16, NL), blk>>>(W1, W1T, DD, FFD);
        transpose_rnd<<<dim3(16, 64, NL), blk>>>(W2, W2T, FFD, DD);
        pack_bias<<<(NL * QKVW + 255) / 256, 256>>>(bq, bk, bv, bqkv);
    }

    init_h_kernel<<<(NN * DD) / 256, 256>>>(x, init_W, init_b, cent, deg);

    const float scale = 1.f / sqrtf((float)DKH);

    for (int l = 0; l < NL; l++) {
        ln_kernel<<<NN, 256>>>(h, hn);

        // packed QKV: [2048,1536] = hn x WqkvT^T
        gemm_mma<128, 5><<<dim3(QKVW / 128, NN / 128), 256, smbytes(128)>>>(
            hn, DD, WqkvT + (size_t)l * QKVW * DD, DD, qkv, QKVW, DD,
            bqkv + (size_t)l * QKVW, nullptr);

        // fused block-diagonal attention
        attn_fused<<<dim3(NG, 2), 128, ATTN_SMEM>>>(qkv, attn, sp, db, vb, scale);

        // h = attn @ Wo + bo + h
        gemm_mma<64, 3><<<dim3(DD / 64, NN / 128), 256, smbytes(64)>>>(
            attn, DD, WoT + (size_t)l * DD * DD, DD, h, DD, DD,
            bo + (size_t)l * DD, h);

        ln_kernel<<<NN, 256>>>(h, hn);

        // ff = relu(hn @ W1 + b1)
        gemm_mma<128, 4><<<dim3(FFD / 128, NN / 128), 256, smbytes(128)>>>(
            hn, DD, W1T + (size_t)l * DD * FFD, DD, ff, FFD, DD,
            b1 + (size_t)l * FFD, nullptr);

        // h = ff @ W2 + b2 + h
        gemm_mma<64, 3><<<dim3(DD / 64, NN / 128), 256, smbytes(64)>>>(
            ff, FFD, W2T + (size_t)l * FFD * DD, FFD, h, DD, FFD,
            b2 + (size_t)l * DD, h);
    }

    copy_out_kernel<<<(NG * DD) / 256, 256>>>((float*)d_out);
}

// round 6
// speedup vs baseline: 6.4367x; 1.1455x over previous
#include <cuda_runtime.h>
#include <math.h>
#include <stdint.h>

#define NG      64
#define N_ORIG  1984
#define NN      2048
#define DD      512
#define NH      8
#define DKH     64
#define FFD     2048
#define NL      4
#define NFE     32
#define MAX_SP  100
#define MAX_DEG 100
#define QKVW    1536

// permutation of k within groups of 8 (applies to BOTH gemm operands)
__host__ __device__ __forceinline__ int permk(int k) {
    return (k & ~7) | ((k & 3) << 1) | ((k >> 2) & 1);
}

// ---------- scratch ----------
__device__ float g_h[NN * DD];
__device__ float g_hn[NN * DD];          // permuted-K layout
__device__ float g_qkv[NN * QKVW];       // normal layout
__device__ float g_attn[NN * DD];        // permuted-K layout
__device__ float g_ff[(size_t)NN * FFD]; // permuted-K layout
__device__ float g_WqkvT[NL * QKVW * DD];  // permuted
__device__ float g_bqkv[NL * QKVW];
__device__ float g_WoT[NL * DD * DD];      // permuted
__device__ float g_W1T[NL * DD * FFD];     // permuted
__device__ float g_W2T[NL * FFD * DD];     // permuted

// ---------- helpers ----------
__device__ __forceinline__ uint32_t smem_u32(const void* p) {
    uint32_t a;
    asm("{ .reg .u64 t; cvta.to.shared.u64 t, %1; cvt.u32.u64 %0, t; }" : "=r"(a) : "l"(p));
    return a;
}
__device__ __forceinline__ float rnd_tf32(float x) {
    uint32_t r; asm("cvt.rna.tf32.f32 %0, %1;" : "=r"(r) : "f"(x));
    return __uint_as_float(r);
}
__device__ __forceinline__ void cp_async16(uint32_t d, const void* g) {
    asm volatile("cp.async.cg.shared.global [%0], [%1], 16;" :: "r"(d), "l"(g));
}
__device__ __forceinline__ void cp_commit() { asm volatile("cp.async.commit_group;" ::: "memory"); }
__device__ __forceinline__ void cp_wait1()  { asm volatile("cp.async.wait_group 1;"  ::: "memory"); }
__device__ __forceinline__ void cp_wait0()  { asm volatile("cp.async.wait_group 0;"  ::: "memory"); }
__device__ __forceinline__ void lds64(uint32_t addr, uint32_t& x, uint32_t& y) {
    asm volatile("ld.shared.v2.u32 {%0,%1}, [%2];" : "=r"(x), "=r"(y) : "r"(addr));
}
// swizzled tile: byte = (row*128 + pos*4) ^ ((row&3)<<5)
__device__ __forceinline__ uint32_t taddr(uint32_t base, int row, int pos) {
    return base + ((((uint32_t)row << 7) + ((uint32_t)pos << 2)) ^ (((uint32_t)row & 3u) << 5));
}
__device__ __forceinline__ void mma8(float* c, const uint32_t* a, const uint32_t* b) {
    asm volatile(
        "mma.sync.aligned.m16n8k8.row.col.f32.tf32.tf32.f32 "
        "{%0,%1,%2,%3}, {%4,%5,%6,%7}, {%8,%9}, {%0,%1,%2,%3};"
        : "+f"(c[0]), "+f"(c[1]), "+f"(c[2]), "+f"(c[3])
        : "r"(a[0]), "r"(a[1]), "r"(a[2]), "r"(a[3]), "r"(b[0]), "r"(b[1]));
}

// ---------- small kernels ----------
__global__ void init_h_kernel(const float* __restrict__ x, const float* __restrict__ W,
                              const float* __restrict__ b, const float* __restrict__ cent,
                              const int* __restrict__ deg)
{
    int idx = blockIdx.x * blockDim.x + threadIdx.x;
    if (idx >= NN * DD) return;
    int n = idx / DD, d = idx % DD;
    float v = 0.f;
    if (n < N_ORIG) {
        v = b[d];
        #pragma unroll
        for (int f = 0; f < NFE; f++) v += x[n * NFE + f] * W[f * DD + d];
    }
    g_h[idx] = v + cent[min(deg[n], MAX_DEG) * DD + d];
}

// LN; output written in permuted-K layout
__global__ void ln_kernel(const float* __restrict__ in, float* __restrict__ out)
{
    __shared__ float s1[256], s2[256];
    int row = blockIdx.x, t = threadIdx.x;
    const float* p = in + (size_t)row * DD;
    float a = 0.f, q = 0.f;
    for (int j = t; j < DD; j += 256) { float v = p[j]; a += v; q += v * v; }
    s1[t] = a; s2[t] = q; __syncthreads();
    for (int s = 128; s > 0; s >>= 1) {
        if (t < s) { s1[t] += s1[t + s]; s2[t] += s2[t + s]; }
        __syncthreads();
    }
    float mean = s1[0] * (1.f / DD);
    float var  = s2[0] * (1.f / DD) - mean * mean;
    float r = rsqrtf(var + 1e-5f);
    float* o = out + (size_t)row * DD;
    for (int j = t; j < DD; j += 256) o[permk(j)] = rnd_tf32((p[j] - mean) * r);
}

// out[z][C][permk(R-idx)] = rnd(in[z][R][C])
__global__ void transpose_rnd(const float* __restrict__ in, float* __restrict__ out, int R, int C)
{
    __shared__ float t[32][33];
    size_t zoff = (size_t)blockIdx.z * R * C;
    in += zoff; out += zoff;
    int c0 = blockIdx.x * 32, r0 = blockIdx.y * 32;
    for (int i = threadIdx.y; i < 32; i += 8)
        t[i][threadIdx.x] = in[(size_t)(r0 + i) * C + c0 + threadIdx.x];
    __syncthreads();
    for (int i = threadIdx.y; i < 32; i += 8)
        out[(size_t)(c0 + i) * R + permk(r0 + threadIdx.x)] = rnd_tf32(t[threadIdx.x][i]);
}

// pack Wq/Wk/Wv -> WqkvT[l][qkv*512 + h*64 + n][permk(d)]
__global__ void pack_qkvT(const float* __restrict__ Wq, const float* __restrict__ Wk,
                          const float* __restrict__ Wv, float* __restrict__ out)
{
    __shared__ float t[32][33];
    int z = blockIdx.z;
    int h = z & 7, qkv = (z >> 3) % 3, l = z / 24;
    const float* src = (qkv == 0 ? Wq : qkv == 1 ? Wk : Wv) + (size_t)(l * NH + h) * DD * DKH;
    float* dst = out + (size_t)l * QKVW * DD + (size_t)(qkv * DD + h * DKH) * DD;
    int c0 = blockIdx.x * 32, r0 = blockIdx.y * 32;
    for (int i = threadIdx.y; i < 32; i += 8)
        t[i][threadIdx.x] = src[(size_t)(r0 + i) * DKH + c0 + threadIdx.x];
    __syncthreads();
    for (int i = threadIdx.y; i < 32; i += 8)
        dst[(size_t)(c0 + i) * DD + permk(r0 + threadIdx.x)] = rnd_tf32(t[threadIdx.x][i]);
}

__global__ void pack_bias(const float* __restrict__ bq, const float* __restrict__ bk,
                          const float* __restrict__ bv, float* __restrict__ out)
{
    int idx = blockIdx.x * blockDim.x + threadIdx.x;
    if (idx >= NL * QKVW) return;
    int l = idx / QKVW, p = idx % QKVW;
    float v;
    if (p < DD)            v = bq[l * DD + p];
    else if (p < 2 * DD)   v = bk[l * DD + p - DD];
    else                   v = bv[l * DD + p - 2 * DD];
    out[idx] = v;
}

__global__ void copy_out_kernel(float* __restrict__ out)
{
    int i = blockIdx.x * blockDim.x + threadIdx.x;
    if (i < NG * DD) out[i] = g_h[N_ORIG * DD + i];
}

// ---------- fused block-diagonal attention (output permuted-K) ----------
__global__ void __launch_bounds__(128)
attn_fused(const float* __restrict__ qkv, float* __restrict__ O,
           const int* __restrict__ sp, const float* __restrict__ db,
           const float* __restrict__ vb, float scale)
{
    extern __shared__ float sm[];
    const int g = blockIdx.x;
    const int w = threadIdx.x >> 5, lane = threadIdx.x & 31;
    const int h = blockIdx.y * 4 + w;
    float* Ks = sm + w * 2048;
    float* Ps = sm + 4 * 2048 + w * 1056;
    float* Bs = sm + 4 * 2048 + 4 * 1056;

    for (int t = threadIdx.x; t < 32 * 32; t += 128) {
        int r = t >> 5, c = t & 31;
        int i = (r < 31) ? g * 31 + r : N_ORIG + g;
        int j = (c < 31) ? g * 31 + c : N_ORIG + g;
        float bvv;
        if (i == j)                      bvv = db[0];
        else if ((r == 31) != (c == 31)) bvv = vb[0];
        else                             bvv = db[min(sp[(size_t)i * N_ORIG + j], MAX_SP)];
        Bs[r * 33 + c] = bvv;
    }
    __syncthreads();

    for (int t = lane; t < 512; t += 32) {
        int c = t >> 4, kq = t & 15;
        int n = (c < 31) ? g * 31 + c : N_ORIG + g;
        const float4 v4 = *(const float4*)(qkv + (size_t)n * QKVW + DD + h * DKH + kq * 4);
        *(float4*)(Ks + c * 64 + kq * 4) = v4;
    }
    __syncwarp();

    const int r = lane;
    const int nr = (r < 31) ? g * 31 + r : N_ORIG + g;
    const float4* qp = (const float4*)(qkv + (size_t)nr * QKVW + h * DKH);
    float4 q[16];
    #pragma unroll
    for (int i = 0; i < 16; i++) q[i] = qp[i];

    float s[32];
    #pragma unroll
    for (int c = 0; c < 32; c++) {
        const float2* kr = (const float2*)(Ks + c * 64);
        float acc = 0.f;
        #pragma unroll
        for (int i = 0; i < 16; i++) {
            float2 a = kr[2 * i], b = kr[2 * i + 1];
            acc += q[i].x * a.x + q[i].y * a.y + q[i].z * b.x + q[i].w * b.y;
        }
        s[c] = acc * scale + Bs[r * 33 + c];
    }
    float m = s[0];
    #pragma unroll
    for (int c = 1; c < 32; c++) m = fmaxf(m, s[c]);
    float sum = 0.f;
    #pragma unroll
    for (int c = 0; c < 32; c++) { s[c] = __expf(s[c] - m); sum += s[c]; }
    float inv = 1.f / sum;
    #pragma unroll
    for (int c = 0; c < 32; c++) Ps[r * 33 + c] = s[c] * inv;
    __syncwarp();

    float va[32], vb2[32];
    #pragma unroll
    for (int c = 0; c < 32; c++) {
        int n = (c < 31) ? g * 31 + c : N_ORIG + g;
        const float* vp = qkv + (size_t)n * QKVW + 2 * DD + h * DKH;
        va[c]  = vp[lane];
        vb2[c] = vp[lane + 32];
    }

    const int pd0 = permk(lane);        // within 64-wide head slice
    const int pd1 = permk(lane + 32);
    for (int rr = 0; rr < 32; rr++) {
        float a0 = 0.f, a1 = 0.f;
        #pragma unroll
        for (int c = 0; c < 32; c++) {
            float p = Ps[rr * 33 + c];
            a0 += p * va[c];
            a1 += p * vb2[c];
        }
        int n = (rr < 31) ? g * 31 + rr : N_ORIG + g;
        float* op = O + (size_t)n * DD + h * DKH;
        op[pd0] = rnd_tf32(a0);
        op[pd1] = rnd_tf32(a1);
    }
}

// ---------- staging ----------
template<int TN>
__device__ __forceinline__ void load_tiles(const float* A, int lda, const float* Bt, int ldb,
        int row0, int col0, int k0, uint32_t aS, uint32_t bS, int tid)
{
    #pragma unroll
    for (int i = 0; i < 4; i++) {
        int u = tid + i * 256;
        int r = u >> 3, q = u & 7;
        uint32_t off = ((((uint32_t)r << 7) + ((uint32_t)q << 4)) ^ (((uint32_t)r & 3u) << 5));
        cp_async16(aS + off, A + (size_t)(row0 + r) * lda + k0 + q * 4);
    }
    #pragma unroll
    for (int i = 0; i < TN / 32; i++) {
        int u = tid + i * 256;
        int r = u >> 3, q = u & 7;
        uint32_t off = ((((uint32_t)r << 7) + ((uint32_t)q << 4)) ^ (((uint32_t)r & 3u) << 5));
        cp_async16(bS + off, Bt + (size_t)(col0 + r) * ldb + k0 + q * 4);
    }
}

// ---------- tf32 mma.sync NT GEMM, 3-stage pipeline, permuted-K operands ----------
// MODE 3: +bias[c]+res[r][c], normal out | 4: rnd(relu(+bias[c])), PERMUTED out | 5: +bias[c], normal out
template<int TN, int MODE>
__global__ void __launch_bounds__(256)
gemm_mma(const float* __restrict__ A, int lda,
         const float* __restrict__ Bt, int ldb,
         float* __restrict__ C, int ldc,
         int K,
         const float* __restrict__ bias,
         const float* __restrict__ res)
{
    constexpr int WC = TN / 64;
    constexpr int WR = 8 / WC;
    constexpr int WROWS = 128 / WR;
    constexpr int MT = WROWS / 16;
    constexpr uint32_t STAGE = (128u + TN) * 32u * 4u;

    extern __shared__ char smraw[];
    uint32_t rawu = smem_u32(smraw);
    uint32_t base = (rawu + 127u) & ~127u;

    const int tid = threadIdx.x;
    const int col0 = blockIdx.x * TN;
    const int row0 = blockIdx.y * 128;

    const int w = tid >> 5, lane = tid & 31;
    const int wr = w / WC, wc = w % WC;
    const int g = lane >> 2, cq = lane & 3;

    float acc[MT][8][4];
    #pragma unroll
    for (int mt = 0; mt < MT; mt++)
        #pragma unroll
        for (int nt = 0; nt < 8; nt++)
            #pragma unroll
            for (int i = 0; i < 4; i++) acc[mt][nt][i] = 0.f;

    const int nc = K >> 5;
    // prologue: chunks 0,1 into stages 0,1
    {
        uint32_t aS = base, bS = base + 128u * 32u * 4u;
        load_tiles<TN>(A, lda, Bt, ldb, row0, col0, 0, aS, bS, tid);
        cp_commit();
        aS = base + STAGE; bS = aS + 128u * 32u * 4u;
        load_tiles<TN>(A, lda, Bt, ldb, row0, col0, 32, aS, bS, tid);
        cp_commit();
    }

    int s = 0;
    for (int c = 0; c < nc; c++) {
        if (c + 1 < nc) cp_wait1(); else cp_wait0();
        __syncthreads();
        if (c + 2 < nc) {
            int s2 = s + 2; if (s2 >= 3) s2 -= 3;
            uint32_t aS2 = base + (uint32_t)s2 * STAGE, bS2 = aS2 + 128u * 32u * 4u;
            load_tiles<TN>(A, lda, Bt, ldb, row0, col0, (c + 2) << 5, aS2, bS2, tid);
            cp_commit();
        }
        uint32_t aS = base + (uint32_t)s * STAGE, bS = aS + 128u * 32u * 4u;
        #pragma unroll
        for (int kk = 0; kk < 4; kk++) {
            const int pb = kk * 8 + cq * 2;
            uint32_t afr[MT][4];
            #pragma unroll
            for (int mt = 0; mt < MT; mt++) {
                int rb = wr * WROWS + mt * 16 + g;
                lds64(taddr(aS, rb,     pb), afr[mt][0], afr[mt][2]);
                lds64(taddr(aS, rb + 8, pb), afr[mt][1], afr[mt][3]);
            }
            uint32_t bfr[8][2];
            #pragma unroll
            for (int nt = 0; nt < 8; nt++) {
                int nb = wc * 64 + nt * 8 + g;
                lds64(taddr(bS, nb, pb), bfr[nt][0], bfr[nt][1]);
            }
            #pragma unroll
            for (int mt = 0; mt < MT; mt++)
                #pragma unroll
                for (int nt = 0; nt < 8; nt++)
                    mma8(acc[mt][nt], afr[mt], bfr[nt]);
        }
        if (++s >= 3) s -= 3;
    }

    #pragma unroll
    for (int mt = 0; mt < MT; mt++) {
        #pragma unroll
        for (int nt = 0; nt < 8; nt++) {
            int cc = col0 + wc * 64 + nt * 8 + cq * 2;
            #pragma unroll
            for (int half = 0; half < 2; half++) {
                int r = row0 + wr * WROWS + mt * 16 + g + half * 8;
                float v0 = acc[mt][nt][half * 2];
                float v1 = acc[mt][nt][half * 2 + 1];
                v0 += bias[cc]; v1 += bias[cc + 1];
                if (MODE == 3) {
                    v0 += res[(size_t)r * ldc + cc];
                    v1 += res[(size_t)r * ldc + cc + 1];
                }
                if (MODE == 4) {
                    // permuted output (feeds next GEMM's A)
                    C[(size_t)r * ldc + permk(cc)]     = rnd_tf32(fmaxf(v0, 0.f));
                    C[(size_t)r * ldc + permk(cc + 1)] = rnd_tf32(fmaxf(v1, 0.f));
                } else {
                    float2 o; o.x = v0; o.y = v1;
                    *(float2*)(C + (size_t)r * ldc + cc) = o;
                }
            }
        }
    }
}

// ---------- launch ----------
static inline int smbytes3(int tn) { return 128 + 3 * (128 + tn) * 32 * 4; }
#define ATTN_SMEM ((4 * 2048 + 4 * 1056 + 1056) * 4)

extern "C" void kernel_launch(void* const* d_in, const int* in_sizes, int n_in,
                              void* d_out, int out_size)
{
    const float* x      = (const float*)d_in[0];
    const int*   sp     = (const int*)  d_in[1];
    const int*   deg    = (const int*)  d_in[3];
    const float* init_W = (const float*)d_in[4];
    const float* init_b = (const float*)d_in[5];
    const float* cent   = (const float*)d_in[6];
    const float* db     = (const float*)d_in[7];
    const float* vb     = (const float*)d_in[8];
    const float* Wq     = (const float*)d_in[9];
    const float* bq     = (const float*)d_in[10];
    const float* Wk     = (const float*)d_in[11];
    const float* bk     = (const float*)d_in[12];
    const float* Wv     = (const float*)d_in[13];
    const float* bv     = (const float*)d_in[14];
    const float* Wo     = (const float*)d_in[15];
    const float* bo     = (const float*)d_in[16];
    const float* W1     = (const float*)d_in[17];
    const float* b1     = (const float*)d_in[18];
    const float* W2     = (const float*)d_in[19];
    const float* b2     = (const float*)d_in[20];

    float *h, *hn, *qkv, *attn, *ff, *WqkvT, *bqkv, *WoT, *W1T, *W2T;
    cudaGetSymbolAddress((void**)&h, g_h);
    cudaGetSymbolAddress((void**)&hn, g_hn);
    cudaGetSymbolAddress((void**)&qkv, g_qkv);
    cudaGetSymbolAddress((void**)&attn, g_attn);
    cudaGetSymbolAddress((void**)&ff, g_ff);
    cudaGetSymbolAddress((void**)&WqkvT, g_WqkvT);
    cudaGetSymbolAddress((void**)&bqkv, g_bqkv);
    cudaGetSymbolAddress((void**)&WoT, g_WoT);
    cudaGetSymbolAddress((void**)&W1T, g_W1T);
    cudaGetSymbolAddress((void**)&W2T, g_W2T);

    cudaFuncSetAttribute(gemm_mma<128, 5>, cudaFuncAttributeMaxDynamicSharedMemorySize, smbytes3(128));
    cudaFuncSetAttribute(gemm_mma<128, 4>, cudaFuncAttributeMaxDynamicSharedMemorySize, smbytes3(128));
    cudaFuncSetAttribute(gemm_mma<64, 3>,  cudaFuncAttributeMaxDynamicSharedMemorySize, smbytes3(64));
    cudaFuncSetAttribute(attn_fused, cudaFuncAttributeMaxDynamicSharedMemorySize, ATTN_SMEM);

    {
        dim3 blk(32, 8);
        pack_qkvT<<<dim3(2, 16, NL * 3 * NH), blk>>>(Wq, Wk, Wv, WqkvT);
        transpose_rnd<<<dim3(16, 16, NL), blk>>>(Wo, WoT, DD, DD);
        transpose_rnd<<<dim3(64, 16, NL), blk>>>(W1, W1T, DD, FFD);
        transpose_rnd<<<dim3(16, 64, NL), blk>>>(W2, W2T, FFD, DD);
        pack_bias<<<(NL * QKVW + 255) / 256, 256>>>(bq, bk, bv, bqkv);
    }

    init_h_kernel<<<(NN * DD) / 256, 256>>>(x, init_W, init_b, cent, deg);

    const float scale = 1.f / sqrtf((float)DKH);

    for (int l = 0; l < NL; l++) {
        ln_kernel<<<NN, 256>>>(h, hn);

        gemm_mma<128, 5><<<dim3(QKVW / 128, NN / 128), 256, smbytes3(128)>>>(
            hn, DD, WqkvT + (size_t)l * QKVW * DD, DD, qkv, QKVW, DD,
            bqkv + (size_t)l * QKVW, nullptr);

        attn_fused<<<dim3(NG, 2), 128, ATTN_SMEM>>>(qkv, attn, sp, db, vb, scale);

        gemm_mma<64, 3><<<dim3(DD / 64, NN / 128), 256, smbytes3(64)>>>(
            attn, DD, WoT + (size_t)l * DD * DD, DD, h, DD, DD,
            bo + (size_t)l * DD, h);

        ln_kernel<<<NN, 256>>>(h, hn);

        gemm_mma<128, 4><<<dim3(FFD / 128, NN / 128), 256, smbytes3(128)>>>(
            hn, DD, W1T + (size_t)l * DD * FFD, DD, ff, FFD, DD,
            b1 + (size_t)l * FFD, nullptr);

        gemm_mma<64, 3><<<dim3(DD / 64, NN / 128), 256, smbytes3(64)>>>(
            ff, FFD, W2T + (size_t)l * FFD * DD, FFD, h, DD, FFD,
            b2 + (size_t)l * DD, h);
    }

    copy_out_kernel<<<(NG * DD) / 256, 256>>>((float*)d_out);
}